// round 10
// baseline (speedup 1.0000x reference)
#include <cuda_runtime.h>
#include <cuda_fp16.h>
#include <math.h>
#include <stdint.h>

#define S_LEN 2048
#define EMB   1024
#define NH    16
#define HD    64
#define BATCH 2
#define M_TOK (BATCH * S_LEN)   // 4096

// ---------------- scratch (device globals) ---------------------------------
__device__ __half g_qh[BATCH * NH * S_LEN * HD];  // half [B,H,S,D]
__device__ __half g_kh[BATCH * NH * S_LEN * HD];
__device__ __half g_vh[BATCH * NH * S_LEN * HD];
__device__ __half g_xh[(size_t)M_TOK * EMB];      // half x [4096,1024]
__device__ __half g_wh[4 * EMB * EMB];            // half Wq|Wk|Wv | Wo
__device__ __half g_atth[(size_t)M_TOK * EMB];    // half attn out [B,S,E]

// ---------------- PTX helpers ----------------------------------------------
__device__ __forceinline__ uint32_t smem_u32(const void* p) {
    uint32_t a;
    asm("{ .reg .u64 t; cvta.to.shared.u64 t, %1; cvt.u32.u64 %0, t; }"
        : "=r"(a) : "l"(p));
    return a;
}
__device__ __forceinline__ void cp16(uint32_t s, const void* g) {
    asm volatile("cp.async.cg.shared.global [%0], [%1], 16;" :: "r"(s), "l"(g) : "memory");
}
__device__ __forceinline__ void cp_commit() {
    asm volatile("cp.async.commit_group;" ::: "memory");
}
#define CP_WAIT(n) asm volatile("cp.async.wait_group %0;" :: "n"(n) : "memory")

__device__ __forceinline__ void ldsm4(uint32_t* r, uint32_t addr) {
    asm volatile("ldmatrix.sync.aligned.m8n8.x4.shared.b16 {%0,%1,%2,%3}, [%4];"
                 : "=r"(r[0]), "=r"(r[1]), "=r"(r[2]), "=r"(r[3]) : "r"(addr));
}
__device__ __forceinline__ void ldsm4t(uint32_t* r, uint32_t addr) {
    asm volatile("ldmatrix.sync.aligned.m8n8.x4.trans.shared.b16 {%0,%1,%2,%3}, [%4];"
                 : "=r"(r[0]), "=r"(r[1]), "=r"(r[2]), "=r"(r[3]) : "r"(addr));
}
__device__ __forceinline__ void mma_h(float* c, const uint32_t* a,
                                      uint32_t b0, uint32_t b1) {
    asm volatile(
        "mma.sync.aligned.m16n8k16.row.col.f32.f16.f16.f32 "
        "{%0,%1,%2,%3}, {%4,%5,%6,%7}, {%8,%9}, {%0,%1,%2,%3};"
        : "+f"(c[0]), "+f"(c[1]), "+f"(c[2]), "+f"(c[3])
        : "r"(a[0]), "r"(a[1]), "r"(a[2]), "r"(a[3]), "r"(b0), "r"(b1));
}
__device__ __forceinline__ uint32_t pack2(float a, float b) {
    __half2 h = __floats2half2_rn(a, b);
    return *reinterpret_cast<uint32_t*>(&h);
}
__device__ __forceinline__ float ex2(float x) {
    float y;
    asm("ex2.approx.ftz.f32 %0, %1;" : "=f"(y) : "f"(x));
    return y;
}
// packed half2 exp2: one MUFU op for two elements
__device__ __forceinline__ uint32_t ex2h2(uint32_t x) {
    uint32_t y;
    asm("ex2.approx.f16x2 %0, %1;" : "=r"(y) : "r"(x));
    return y;
}
__device__ __forceinline__ float2 h2f2(uint32_t h) {
    __half2 hh = *reinterpret_cast<__half2*>(&h);
    return __half22float2(hh);
}

// ---------------------------------------------------------------------------
// Fused fp32->half conversion of x and the 4 weights (one launch).
// ---------------------------------------------------------------------------
__global__ __launch_bounds__(256) void conv_all(const float* __restrict__ x,
                                                const float* __restrict__ Wq,
                                                const float* __restrict__ Wk,
                                                const float* __restrict__ Wv,
                                                const float* __restrict__ Wo,
                                                __half* __restrict__ xh,
                                                __half* __restrict__ wh)
{
    int u = blockIdx.x * 256 + threadIdx.x;     // float4 units, 2M total
    const float* src;
    __half* dst;
    int off;
    if (u < (1 << 20)) { src = x; dst = xh; off = u; }
    else {
        int w = (u - (1 << 20)) >> 18;          // 0..3
        off = (u - (1 << 20)) & ((1 << 18) - 1);
        src = (w == 0) ? Wq : (w == 1) ? Wk : (w == 2) ? Wv : Wo;
        dst = wh + (size_t)w * EMB * EMB;
    }
    float4 v = *(const float4*)&src[off * 4];
    uint2 o;
    o.x = pack2(v.x, v.y);
    o.y = pack2(v.z, v.w);
    *(uint2*)&dst[off * 4] = o;
}

// ---------------------------------------------------------------------------
// half mma GEMM v3: warp tile 64x64, 4 warps, CTA tile 128x128.
// 2-stage cp.async pipeline (64KB smem) -> 3 CTAs/SM.
// ---------------------------------------------------------------------------
#define GSMEM (2 * 32768)

__global__ __launch_bounds__(128, 3) void gemm_h2(const __half* __restrict__ A,
                                                  const __half* __restrict__ W,
                                                  float* __restrict__ Cf,
                                                  __half* __restrict__ Qo,
                                                  __half* __restrict__ Ko,
                                                  __half* __restrict__ Vo,
                                                  int mode)
{
    extern __shared__ char smx[];
    const uint32_t sb = smem_u32(smx);
    const int tid = threadIdx.x, wid = tid >> 5, lane = tid & 31;
    const int bn0 = blockIdx.x * 128, bm0 = blockIdx.y * 128;
    const int wm = (wid & 1) * 64, wn = (wid >> 1) * 64;

    const int g = lane >> 3;
    const int arow = (g & 1) * 8 + (lane & 7);
    const int ac16 = g >> 1;
    const int brow = (g >> 1) * 8 + (lane & 7);
    const int bc16 = g & 1;

    auto load = [&](int ck, int st) {
        uint32_t Ab = sb + st * 32768, Bb = Ab + 16384;
#pragma unroll
        for (int j = 0; j < 8; j++) {
            int idx = tid + j * 128;
            int r = idx >> 3, c16 = idx & 7;
            uint32_t sw = (uint32_t)(r * 128) + (uint32_t)((c16 ^ (r & 7)) << 4);
            cp16(Ab + sw, A + (size_t)(bm0 + r) * 1024 + ck * 64 + c16 * 8);
            cp16(Bb + sw, W + (size_t)(bn0 + r) * 1024 + ck * 64 + c16 * 8);
        }
        cp_commit();
    };
    load(0, 0); load(1, 1);

    float acc[4][8][4];
#pragma unroll
    for (int mb = 0; mb < 4; mb++)
#pragma unroll
        for (int nf = 0; nf < 8; nf++)
#pragma unroll
            for (int i = 0; i < 4; i++) acc[mb][nf][i] = 0.0f;

    for (int c = 0; c < 16; c++) {
        int st = c & 1;
        if (c < 15) { CP_WAIT(1); }
        else        { CP_WAIT(0); }
        __syncthreads();

        uint32_t Ab = sb + st * 32768, Bb = Ab + 16384;
#pragma unroll
        for (int ks = 0; ks < 4; ks++) {
            uint32_t af[4][4];
#pragma unroll
            for (int mb = 0; mb < 4; mb++) {
                int row = wm + mb * 16 + arow;
                ldsm4(af[mb], Ab + row * 128 + (((2 * ks + ac16) ^ (row & 7)) << 4));
            }
#pragma unroll
            for (int pn = 0; pn < 4; pn++) {
                uint32_t bf[4];
                int rowb = wn + pn * 16 + brow;
                ldsm4(bf, Bb + rowb * 128 + (((2 * ks + bc16) ^ (rowb & 7)) << 4));
#pragma unroll
                for (int mb = 0; mb < 4; mb++) {
                    mma_h(acc[mb][2 * pn],     af[mb], bf[0], bf[1]);
                    mma_h(acc[mb][2 * pn + 1], af[mb], bf[2], bf[3]);
                }
            }
        }
        __syncthreads();
        if (c + 2 < 16) load(c + 2, st);
    }

#pragma unroll
    for (int mb = 0; mb < 4; mb++) {
        int m0 = bm0 + wm + mb * 16 + (lane >> 2);
#pragma unroll
        for (int nf = 0; nf < 8; nf++) {
            int n0 = bn0 + wn + nf * 8 + 2 * (lane & 3);
            if (mode == 0) {
                *(float2*)&Cf[(size_t)m0 * 1024 + n0] =
                    make_float2(acc[mb][nf][0], acc[mb][nf][1]);
                *(float2*)&Cf[(size_t)(m0 + 8) * 1024 + n0] =
                    make_float2(acc[mb][nf][2], acc[mb][nf][3]);
            } else {
                int proj = n0 >> 10;
                int within = n0 & 1023;
                int h = within >> 6, d = within & 63;
                __half* dstp = (proj == 0) ? Qo : (proj == 1) ? Ko : Vo;
#pragma unroll
                for (int rr = 0; rr < 2; rr++) {
                    int m = m0 + 8 * rr;
                    int b = m >> 11, s2 = m & 2047;
                    size_t dst = ((((size_t)(b * NH + h) * S_LEN + s2)) << 6) + d;
                    *(uint32_t*)&dstp[dst] =
                        pack2(acc[mb][nf][rr * 2], acc[mb][nf][rr * 2 + 1]);
                }
            }
        }
    }
}

// ---------------------------------------------------------------------------
// RoPE in-place; q additionally scaled by 0.125 * log2(e) (exp2 softmax).
// ---------------------------------------------------------------------------
#define QSCALE 0.180336879f   // 0.125 * log2(e)

__global__ __launch_bounds__(256) void rope_h(__half* __restrict__ qh,
                                              __half* __restrict__ kh)
{
    int t = blockIdx.x * blockDim.x + threadIdx.x;
    int i  = t & 31;
    int s  = (t >> 5) & (S_LEN - 1);
    int bh = t >> 16;
    float inv_freq = powf(10000.0f, -(float)i * (1.0f / 32.0f));
    float theta = (float)s * inv_freq;
    float sn, cs;
    sincosf(theta, &sn, &cs);
    size_t base = ((size_t)bh * S_LEN + s) * HD;
    float q1 = __half2float(qh[base + i]), q2 = __half2float(qh[base + i + 32]);
    qh[base + i]      = __float2half((q1 * cs - q2 * sn) * QSCALE);
    qh[base + i + 32] = __float2half((q2 * cs + q1 * sn) * QSCALE);
    float k1 = __half2float(kh[base + i]), k2 = __half2float(kh[base + i + 32]);
    kh[base + i]      = __float2half(k1 * cs - k2 * sn);
    kh[base + i + 32] = __float2half(k2 * cs + k1 * sn);
}

// ---------------------------------------------------------------------------
// Causal flash attention v4: 4 warps / 64 q-rows per CTA, f16x2 exp2 softmax
// (P emerges directly in A-fragment layout), single masked diagonal tile.
// smem: Q 8KB | K 2x8KB | V 2x8KB = 40KB
// ---------------------------------------------------------------------------
#define FSMEM (8192 + 16384 + 16384)

__global__ __launch_bounds__(128, 4) void flash_h(const __half* __restrict__ Q,
                                                  const __half* __restrict__ K,
                                                  const __half* __restrict__ V,
                                                  __half* __restrict__ O)
{
    extern __shared__ char smx[];
    const uint32_t sb = smem_u32(smx);
    const int tid = threadIdx.x, wid = tid >> 5, lane = tid & 31;
    const int qt = gridDim.x - 1 - blockIdx.x;   // largest tiles first
    const int bh = blockIdx.y;

    const uint32_t Qs  = sb;
    const uint32_t Ks0 = sb + 8192;
    const uint32_t Vs0 = sb + 24576;

    const __half* Qg = Q + ((size_t)bh * S_LEN + qt * 64) * HD;
    const __half* Kg = K + (size_t)bh * S_LEN * HD;
    const __half* Vg = V + (size_t)bh * S_LEN * HD;

    const int g = lane >> 3;
    const int arow = (g & 1) * 8 + (lane & 7);
    const int ac16 = g >> 1;
    const int brow = (g >> 1) * 8 + (lane & 7);
    const int bc16 = g & 1;

    auto loadKV = [&](int kt, int st) {
#pragma unroll
        for (int j = 0; j < 4; j++) {
            int idx = tid + j * 128;
            int r = idx >> 3, c16 = idx & 7;
            uint32_t sw = (uint32_t)(r * 128) + (uint32_t)((c16 ^ (r & 7)) << 4);
            cp16(Ks0 + st * 8192 + sw, Kg + (size_t)(kt * 64 + r) * HD + c16 * 8);
            cp16(Vs0 + st * 8192 + sw, Vg + (size_t)(kt * 64 + r) * HD + c16 * 8);
        }
    };

#pragma unroll
    for (int j = 0; j < 4; j++) {
        int idx = tid + j * 128;
        int r = idx >> 3, c16 = idx & 7;
        uint32_t sw = (uint32_t)(r * 128) + (uint32_t)((c16 ^ (r & 7)) << 4);
        cp16(Qs + sw, Qg + (size_t)r * HD + c16 * 8);
    }
    loadKV(0, 0);
    cp_commit();

    uint32_t qf[4][4];
    float accO[8][4];
#pragma unroll
    for (int d = 0; d < 8; d++)
#pragma unroll
        for (int i = 0; i < 4; i++) accO[d][i] = 0.0f;
    float m_r[2] = {-1e30f, -1e30f};
    float l_r[2] = {0.0f, 0.0f};

    for (int kt = 0; kt <= qt; kt++) {
        const int st = kt & 1;
        if (kt < qt) { loadKV(kt + 1, st ^ 1); cp_commit(); CP_WAIT(1); }
        else         { CP_WAIT(0); }
        __syncthreads();

        if (kt == 0) {
#pragma unroll
            for (int ks = 0; ks < 4; ks++) {
                int row = wid * 16 + arow;
                ldsm4(qf[ks], Qs + row * 128 + (((2 * ks + ac16) ^ (row & 7)) << 4));
            }
        }

        const uint32_t Kst = Ks0 + st * 8192;
        const uint32_t Vst = Vs0 + st * 8192;

        // ---- S = Q @ K^T (log2-scaled) -----------------------------------
        float S[8][4];
#pragma unroll
        for (int n = 0; n < 8; n++)
#pragma unroll
            for (int i = 0; i < 4; i++) S[n][i] = 0.0f;

#pragma unroll
        for (int ks = 0; ks < 4; ks++) {
#pragma unroll
            for (int pn = 0; pn < 4; pn++) {
                uint32_t bf[4];
                int rowb = pn * 16 + brow;
                ldsm4(bf, Kst + rowb * 128 + (((2 * ks + bc16) ^ (rowb & 7)) << 4));
                mma_h(S[2 * pn],     qf[ks], bf[0], bf[1]);
                mma_h(S[2 * pn + 1], qf[ks], bf[2], bf[3]);
            }
        }

        // ---- causal mask (single diagonal tile) --------------------------
        if (kt == qt) {
            int rbase = wid * 16 + (lane >> 2);
#pragma unroll
            for (int nf = 0; nf < 8; nf++) {
                int cc = nf * 8 + 2 * (lane & 3);
                if (cc     > rbase)     S[nf][0] = -1e30f;
                if (cc + 1 > rbase)     S[nf][1] = -1e30f;
                if (cc     > rbase + 8) S[nf][2] = -1e30f;
                if (cc + 1 > rbase + 8) S[nf][3] = -1e30f;
            }
        }

        // ---- online softmax (base-2): row maxes first --------------------
        float mn0, mn1, alpha0, alpha1;
        {
            float mx0 = -1e30f, mx1 = -1e30f;
#pragma unroll
            for (int nf = 0; nf < 8; nf++) {
                mx0 = fmaxf(mx0, fmaxf(S[nf][0], S[nf][1]));
                mx1 = fmaxf(mx1, fmaxf(S[nf][2], S[nf][3]));
            }
            mx0 = fmaxf(mx0, __shfl_xor_sync(0xffffffffu, mx0, 1));
            mx0 = fmaxf(mx0, __shfl_xor_sync(0xffffffffu, mx0, 2));
            mx1 = fmaxf(mx1, __shfl_xor_sync(0xffffffffu, mx1, 1));
            mx1 = fmaxf(mx1, __shfl_xor_sync(0xffffffffu, mx1, 2));
            mn0 = fmaxf(m_r[0], mx0);
            mn1 = fmaxf(m_r[1], mx1);
            alpha0 = ex2(m_r[0] - mn0);
            alpha1 = ex2(m_r[1] - mn1);
            m_r[0] = mn0; m_r[1] = mn1;
        }

        // ---- p = exp2(S - m) in half2 (A-fragment layout) + row sums -----
        uint32_t pa[4][4];
        float sum0 = 0.0f, sum1 = 0.0f;
#pragma unroll
        for (int j = 0; j < 4; j++) {
            pa[j][0] = ex2h2(pack2(S[2 * j][0]     - mn0, S[2 * j][1]     - mn0));
            pa[j][1] = ex2h2(pack2(S[2 * j][2]     - mn1, S[2 * j][3]     - mn1));
            pa[j][2] = ex2h2(pack2(S[2 * j + 1][0] - mn0, S[2 * j + 1][1] - mn0));
            pa[j][3] = ex2h2(pack2(S[2 * j + 1][2] - mn1, S[2 * j + 1][3] - mn1));
            float2 f0 = h2f2(pa[j][0]), f1 = h2f2(pa[j][1]);
            float2 f2 = h2f2(pa[j][2]), f3 = h2f2(pa[j][3]);
            sum0 += f0.x + f0.y + f2.x + f2.y;
            sum1 += f1.x + f1.y + f3.x + f3.y;
        }
        sum0 += __shfl_xor_sync(0xffffffffu, sum0, 1);
        sum0 += __shfl_xor_sync(0xffffffffu, sum0, 2);
        sum1 += __shfl_xor_sync(0xffffffffu, sum1, 1);
        sum1 += __shfl_xor_sync(0xffffffffu, sum1, 2);
        l_r[0] = l_r[0] * alpha0 + sum0;
        l_r[1] = l_r[1] * alpha1 + sum1;
#pragma unroll
        for (int df = 0; df < 8; df++) {
            accO[df][0] *= alpha0; accO[df][1] *= alpha0;
            accO[df][2] *= alpha1; accO[df][3] *= alpha1;
        }

        // ---- O += P @ V --------------------------------------------------
#pragma unroll
        for (int j = 0; j < 4; j++) {
#pragma unroll
            for (int pn = 0; pn < 4; pn++) {
                uint32_t bv[4];
                int rowv = j * 16 + arow;
                ldsm4t(bv, Vst + rowv * 128 + (((2 * pn + ac16) ^ (rowv & 7)) << 4));
                mma_h(accO[2 * pn],     pa[j], bv[0], bv[1]);
                mma_h(accO[2 * pn + 1], pa[j], bv[2], bv[3]);
            }
        }
        __syncthreads();
    }

    // ---- epilogue: half att [B,S,E] --------------------------------------
    float inv0 = 1.0f / l_r[0], inv1 = 1.0f / l_r[1];
    int b = bh >> 4, h = bh & 15;
    int r0 = qt * 64 + wid * 16 + (lane >> 2);
#pragma unroll
    for (int df = 0; df < 8; df++) {
        int d = df * 8 + 2 * (lane & 3);
        size_t a0 = ((size_t)(b * S_LEN + r0)) * EMB + h * 64 + d;
        *(uint32_t*)&O[a0] = pack2(accO[df][0] * inv0, accO[df][1] * inv0);
        *(uint32_t*)&O[a0 + (size_t)8 * EMB] =
            pack2(accO[df][2] * inv1, accO[df][3] * inv1);
    }
}

// ---------------------------------------------------------------------------
extern "C" void kernel_launch(void* const* d_in, const int* in_sizes, int n_in,
                              void* d_out, int out_size)
{
    const float* x  = (const float*)d_in[0];
    const float* Wq = (const float*)d_in[1];
    const float* Wk = (const float*)d_in[2];
    const float* Wv = (const float*)d_in[3];
    const float* Wo = (const float*)d_in[4];
    float* out = (float*)d_out;

    __half *qh, *kh, *vh, *xh, *wh, *atth;
    cudaGetSymbolAddress((void**)&qh,   g_qh);
    cudaGetSymbolAddress((void**)&kh,   g_kh);
    cudaGetSymbolAddress((void**)&vh,   g_vh);
    cudaGetSymbolAddress((void**)&xh,   g_xh);
    cudaGetSymbolAddress((void**)&wh,   g_wh);
    cudaGetSymbolAddress((void**)&atth, g_atth);

    cudaFuncSetAttribute(gemm_h2, cudaFuncAttributeMaxDynamicSharedMemorySize, GSMEM);
    cudaFuncSetAttribute(flash_h, cudaFuncAttributeMaxDynamicSharedMemorySize, FSMEM);

    // one fused conversion pass: x + all four weights (2M float4 units)
    conv_all<<<8192, 256>>>(x, Wq, Wk, Wv, Wo, xh, wh);

    // merged QKV projection: N = 3072
    gemm_h2<<<dim3(24, 32), 128, GSMEM>>>(xh, wh, nullptr, qh, kh, vh, 1);

    rope_h<<<(BATCH * NH * S_LEN * 32) / 256, 256>>>(qh, kh);

    flash_h<<<dim3(S_LEN / 64, BATCH * NH), 128, FSMEM>>>(qh, kh, vh, atth);

    // output projection
    gemm_h2<<<dim3(8, 32), 128, GSMEM>>>(atth, wh + (size_t)3 * EMB * EMB,
                                         out, nullptr, nullptr, nullptr, 0);
}

// round 11
// speedup vs baseline: 1.0420x; 1.0420x over previous
#include <cuda_runtime.h>
#include <cuda_fp16.h>
#include <math.h>
#include <stdint.h>

#define S_LEN 2048
#define EMB   1024
#define NH    16
#define HD    64
#define BATCH 2
#define M_TOK (BATCH * S_LEN)   // 4096

// ---------------- scratch (device globals) ---------------------------------
__device__ __half g_qh[BATCH * NH * S_LEN * HD];  // half [B,H,S,D]
__device__ __half g_kh[BATCH * NH * S_LEN * HD];
__device__ __half g_vh[BATCH * NH * S_LEN * HD];
__device__ __half g_xh[(size_t)M_TOK * EMB];      // half x [4096,1024]
__device__ __half g_wh[4 * EMB * EMB];            // half Wq|Wk|Wv | Wo
__device__ __half g_atth[(size_t)M_TOK * EMB];    // half attn out [B,S,E]

// ---------------- PTX helpers ----------------------------------------------
__device__ __forceinline__ uint32_t smem_u32(const void* p) {
    uint32_t a;
    asm("{ .reg .u64 t; cvta.to.shared.u64 t, %1; cvt.u32.u64 %0, t; }"
        : "=r"(a) : "l"(p));
    return a;
}
__device__ __forceinline__ void cp16(uint32_t s, const void* g) {
    asm volatile("cp.async.cg.shared.global [%0], [%1], 16;" :: "r"(s), "l"(g) : "memory");
}
__device__ __forceinline__ void cp_commit() {
    asm volatile("cp.async.commit_group;" ::: "memory");
}
#define CP_WAIT(n) asm volatile("cp.async.wait_group %0;" :: "n"(n) : "memory")

__device__ __forceinline__ void ldsm4(uint32_t* r, uint32_t addr) {
    asm volatile("ldmatrix.sync.aligned.m8n8.x4.shared.b16 {%0,%1,%2,%3}, [%4];"
                 : "=r"(r[0]), "=r"(r[1]), "=r"(r[2]), "=r"(r[3]) : "r"(addr));
}
__device__ __forceinline__ void ldsm4t(uint32_t* r, uint32_t addr) {
    asm volatile("ldmatrix.sync.aligned.m8n8.x4.trans.shared.b16 {%0,%1,%2,%3}, [%4];"
                 : "=r"(r[0]), "=r"(r[1]), "=r"(r[2]), "=r"(r[3]) : "r"(addr));
}
__device__ __forceinline__ void mma_h(float* c, const uint32_t* a,
                                      uint32_t b0, uint32_t b1) {
    asm volatile(
        "mma.sync.aligned.m16n8k16.row.col.f32.f16.f16.f32 "
        "{%0,%1,%2,%3}, {%4,%5,%6,%7}, {%8,%9}, {%0,%1,%2,%3};"
        : "+f"(c[0]), "+f"(c[1]), "+f"(c[2]), "+f"(c[3])
        : "r"(a[0]), "r"(a[1]), "r"(a[2]), "r"(a[3]), "r"(b0), "r"(b1));
}
__device__ __forceinline__ uint32_t pack2(float a, float b) {
    __half2 h = __floats2half2_rn(a, b);
    return *reinterpret_cast<uint32_t*>(&h);
}
__device__ __forceinline__ float ex2(float x) {
    float y;
    asm("ex2.approx.ftz.f32 %0, %1;" : "=f"(y) : "f"(x));
    return y;
}
// packed half2 exp2: one MUFU op for two elements
__device__ __forceinline__ uint32_t ex2h2(uint32_t x) {
    uint32_t y;
    asm("ex2.approx.f16x2 %0, %1;" : "=r"(y) : "r"(x));
    return y;
}
__device__ __forceinline__ float2 h2f2(uint32_t h) {
    __half2 hh = *reinterpret_cast<__half2*>(&h);
    return __half22float2(hh);
}

// ---------------------------------------------------------------------------
// Fused fp32->half conversion of x and the 4 weights (one launch).
// ---------------------------------------------------------------------------
__global__ __launch_bounds__(256) void conv_all(const float* __restrict__ x,
                                                const float* __restrict__ Wq,
                                                const float* __restrict__ Wk,
                                                const float* __restrict__ Wv,
                                                const float* __restrict__ Wo,
                                                __half* __restrict__ xh,
                                                __half* __restrict__ wh)
{
    int u = blockIdx.x * 256 + threadIdx.x;     // float4 units, 2M total
    const float* src;
    __half* dst;
    int off;
    if (u < (1 << 20)) { src = x; dst = xh; off = u; }
    else {
        int w = (u - (1 << 20)) >> 18;          // 0..3
        off = (u - (1 << 20)) & ((1 << 18) - 1);
        src = (w == 0) ? Wq : (w == 1) ? Wk : (w == 2) ? Wv : Wo;
        dst = wh + (size_t)w * EMB * EMB;
    }
    float4 v = *(const float4*)&src[off * 4];
    uint2 o;
    o.x = pack2(v.x, v.y);
    o.y = pack2(v.z, v.w);
    *(uint2*)&dst[off * 4] = o;
}

// ---------------------------------------------------------------------------
// half mma GEMM (R9 config): warp tile 64x64, 4 warps, CTA 128x128,
// 3-stage cp.async pipeline, 2 CTAs/SM. DO NOT TOUCH — at HMMA ceiling.
// ---------------------------------------------------------------------------
#define GSMEM (3 * 32768)

__global__ __launch_bounds__(128, 2) void gemm_h2(const __half* __restrict__ A,
                                                  const __half* __restrict__ W,
                                                  float* __restrict__ Cf,
                                                  __half* __restrict__ Qo,
                                                  __half* __restrict__ Ko,
                                                  __half* __restrict__ Vo,
                                                  int mode)
{
    extern __shared__ char smx[];
    const uint32_t sb = smem_u32(smx);
    const int tid = threadIdx.x, wid = tid >> 5, lane = tid & 31;
    const int bn0 = blockIdx.x * 128, bm0 = blockIdx.y * 128;
    const int wm = (wid & 1) * 64, wn = (wid >> 1) * 64;

    const int g = lane >> 3;
    const int arow = (g & 1) * 8 + (lane & 7);
    const int ac16 = g >> 1;
    const int brow = (g >> 1) * 8 + (lane & 7);
    const int bc16 = g & 1;

    auto load = [&](int ck, int st) {
        uint32_t Ab = sb + st * 32768, Bb = Ab + 16384;
#pragma unroll
        for (int j = 0; j < 8; j++) {
            int idx = tid + j * 128;
            int r = idx >> 3, c16 = idx & 7;
            uint32_t sw = (uint32_t)(r * 128) + (uint32_t)((c16 ^ (r & 7)) << 4);
            cp16(Ab + sw, A + (size_t)(bm0 + r) * 1024 + ck * 64 + c16 * 8);
            cp16(Bb + sw, W + (size_t)(bn0 + r) * 1024 + ck * 64 + c16 * 8);
        }
        cp_commit();
    };
    load(0, 0); load(1, 1); load(2, 2);

    float acc[4][8][4];
#pragma unroll
    for (int mb = 0; mb < 4; mb++)
#pragma unroll
        for (int nf = 0; nf < 8; nf++)
#pragma unroll
            for (int i = 0; i < 4; i++) acc[mb][nf][i] = 0.0f;

    for (int c = 0; c < 16; c++) {
        int st = c % 3;
        if (c < 14)       { CP_WAIT(2); }
        else if (c == 14) { CP_WAIT(1); }
        else              { CP_WAIT(0); }
        __syncthreads();

        uint32_t Ab = sb + st * 32768, Bb = Ab + 16384;
#pragma unroll
        for (int ks = 0; ks < 4; ks++) {
            uint32_t af[4][4];
#pragma unroll
            for (int mb = 0; mb < 4; mb++) {
                int row = wm + mb * 16 + arow;
                ldsm4(af[mb], Ab + row * 128 + (((2 * ks + ac16) ^ (row & 7)) << 4));
            }
#pragma unroll
            for (int pn = 0; pn < 4; pn++) {
                uint32_t bf[4];
                int rowb = wn + pn * 16 + brow;
                ldsm4(bf, Bb + rowb * 128 + (((2 * ks + bc16) ^ (rowb & 7)) << 4));
#pragma unroll
                for (int mb = 0; mb < 4; mb++) {
                    mma_h(acc[mb][2 * pn],     af[mb], bf[0], bf[1]);
                    mma_h(acc[mb][2 * pn + 1], af[mb], bf[2], bf[3]);
                }
            }
        }
        __syncthreads();
        if (c + 3 < 16) load(c + 3, st);
    }

#pragma unroll
    for (int mb = 0; mb < 4; mb++) {
        int m0 = bm0 + wm + mb * 16 + (lane >> 2);
#pragma unroll
        for (int nf = 0; nf < 8; nf++) {
            int n0 = bn0 + wn + nf * 8 + 2 * (lane & 3);
            if (mode == 0) {
                *(float2*)&Cf[(size_t)m0 * 1024 + n0] =
                    make_float2(acc[mb][nf][0], acc[mb][nf][1]);
                *(float2*)&Cf[(size_t)(m0 + 8) * 1024 + n0] =
                    make_float2(acc[mb][nf][2], acc[mb][nf][3]);
            } else {
                int proj = n0 >> 10;
                int within = n0 & 1023;
                int h = within >> 6, d = within & 63;
                __half* dstp = (proj == 0) ? Qo : (proj == 1) ? Ko : Vo;
#pragma unroll
                for (int rr = 0; rr < 2; rr++) {
                    int m = m0 + 8 * rr;
                    int b = m >> 11, s2 = m & 2047;
                    size_t dst = ((((size_t)(b * NH + h) * S_LEN + s2)) << 6) + d;
                    *(uint32_t*)&dstp[dst] =
                        pack2(acc[mb][nf][rr * 2], acc[mb][nf][rr * 2 + 1]);
                }
            }
        }
    }
}

// ---------------------------------------------------------------------------
// RoPE in-place; q additionally scaled by 0.125 * log2(e) (exp2 softmax).
// ---------------------------------------------------------------------------
#define QSCALE 0.180336879f   // 0.125 * log2(e)

__global__ __launch_bounds__(256) void rope_h(__half* __restrict__ qh,
                                              __half* __restrict__ kh)
{
    int t = blockIdx.x * blockDim.x + threadIdx.x;
    int i  = t & 31;
    int s  = (t >> 5) & (S_LEN - 1);
    int bh = t >> 16;
    float inv_freq = powf(10000.0f, -(float)i * (1.0f / 32.0f));
    float theta = (float)s * inv_freq;
    float sn, cs;
    sincosf(theta, &sn, &cs);
    size_t base = ((size_t)bh * S_LEN + s) * HD;
    float q1 = __half2float(qh[base + i]), q2 = __half2float(qh[base + i + 32]);
    qh[base + i]      = __float2half((q1 * cs - q2 * sn) * QSCALE);
    qh[base + i + 32] = __float2half((q2 * cs + q1 * sn) * QSCALE);
    float k1 = __half2float(kh[base + i]), k2 = __half2float(kh[base + i + 32]);
    kh[base + i]      = __float2half(k1 * cs - k2 * sn);
    kh[base + i + 32] = __float2half(k2 * cs + k1 * sn);
}

// ---------------------------------------------------------------------------
// Causal flash attention v5: 4 warps / 64 q-rows, f16x2 exp2 softmax,
// SINGLE barrier per iteration, ballot-gated alpha rescale.
// smem: Q 8KB | K 2x8KB | V 2x8KB = 40KB
// ---------------------------------------------------------------------------
#define FSMEM (8192 + 16384 + 16384)

__global__ __launch_bounds__(128, 4) void flash_h(const __half* __restrict__ Q,
                                                  const __half* __restrict__ K,
                                                  const __half* __restrict__ V,
                                                  __half* __restrict__ O)
{
    extern __shared__ char smx[];
    const uint32_t sb = smem_u32(smx);
    const int tid = threadIdx.x, wid = tid >> 5, lane = tid & 31;
    const int qt = gridDim.x - 1 - blockIdx.x;   // largest tiles first
    const int bh = blockIdx.y;

    const uint32_t Qs  = sb;
    const uint32_t Ks0 = sb + 8192;
    const uint32_t Vs0 = sb + 24576;

    const __half* Qg = Q + ((size_t)bh * S_LEN + qt * 64) * HD;
    const __half* Kg = K + (size_t)bh * S_LEN * HD;
    const __half* Vg = V + (size_t)bh * S_LEN * HD;

    const int g = lane >> 3;
    const int arow = (g & 1) * 8 + (lane & 7);
    const int ac16 = g >> 1;
    const int brow = (g >> 1) * 8 + (lane & 7);
    const int bc16 = g & 1;

    auto loadKV = [&](int kt, int st) {
#pragma unroll
        for (int j = 0; j < 4; j++) {
            int idx = tid + j * 128;
            int r = idx >> 3, c16 = idx & 7;
            uint32_t sw = (uint32_t)(r * 128) + (uint32_t)((c16 ^ (r & 7)) << 4);
            cp16(Ks0 + st * 8192 + sw, Kg + (size_t)(kt * 64 + r) * HD + c16 * 8);
            cp16(Vs0 + st * 8192 + sw, Vg + (size_t)(kt * 64 + r) * HD + c16 * 8);
        }
        cp_commit();
    };

    // prologue: Q tile + KV tile 0 in one group
#pragma unroll
    for (int j = 0; j < 4; j++) {
        int idx = tid + j * 128;
        int r = idx >> 3, c16 = idx & 7;
        uint32_t sw = (uint32_t)(r * 128) + (uint32_t)((c16 ^ (r & 7)) << 4);
        cp16(Qs + sw, Qg + (size_t)r * HD + c16 * 8);
    }
    loadKV(0, 0);

    uint32_t qf[4][4];
    float accO[8][4];
#pragma unroll
    for (int d = 0; d < 8; d++)
#pragma unroll
        for (int i = 0; i < 4; i++) accO[d][i] = 0.0f;
    float m_r[2] = {-1e30f, -1e30f};
    float l_r[2] = {0.0f, 0.0f};

    for (int kt = 0; kt <= qt; kt++) {
        const int st = kt & 1;
        CP_WAIT(0);                 // only loadKV(kt) (+Q at kt=0) in flight
        __syncthreads();            // fill visible + prior-iter reads complete
        if (kt < qt) loadKV(kt + 1, st ^ 1);   // prefetch into opposite buffer

        if (kt == 0) {
#pragma unroll
            for (int ks = 0; ks < 4; ks++) {
                int row = wid * 16 + arow;
                ldsm4(qf[ks], Qs + row * 128 + (((2 * ks + ac16) ^ (row & 7)) << 4));
            }
        }

        const uint32_t Kst = Ks0 + st * 8192;
        const uint32_t Vst = Vs0 + st * 8192;

        // ---- S = Q @ K^T (log2-scaled) -----------------------------------
        float S[8][4];
#pragma unroll
        for (int n = 0; n < 8; n++)
#pragma unroll
            for (int i = 0; i < 4; i++) S[n][i] = 0.0f;

#pragma unroll
        for (int ks = 0; ks < 4; ks++) {
#pragma unroll
            for (int pn = 0; pn < 4; pn++) {
                uint32_t bf[4];
                int rowb = pn * 16 + brow;
                ldsm4(bf, Kst + rowb * 128 + (((2 * ks + bc16) ^ (rowb & 7)) << 4));
                mma_h(S[2 * pn],     qf[ks], bf[0], bf[1]);
                mma_h(S[2 * pn + 1], qf[ks], bf[2], bf[3]);
            }
        }

        // ---- causal mask (single diagonal tile) --------------------------
        if (kt == qt) {
            int rbase = wid * 16 + (lane >> 2);
#pragma unroll
            for (int nf = 0; nf < 8; nf++) {
                int cc = nf * 8 + 2 * (lane & 3);
                if (cc     > rbase)     S[nf][0] = -1e30f;
                if (cc + 1 > rbase)     S[nf][1] = -1e30f;
                if (cc     > rbase + 8) S[nf][2] = -1e30f;
                if (cc + 1 > rbase + 8) S[nf][3] = -1e30f;
            }
        }

        // ---- online softmax (base-2): row maxes ---------------------------
        float mn0, mn1, alpha0, alpha1;
        unsigned need;
        {
            float mx0 = -1e30f, mx1 = -1e30f;
#pragma unroll
            for (int nf = 0; nf < 8; nf++) {
                mx0 = fmaxf(mx0, fmaxf(S[nf][0], S[nf][1]));
                mx1 = fmaxf(mx1, fmaxf(S[nf][2], S[nf][3]));
            }
            mx0 = fmaxf(mx0, __shfl_xor_sync(0xffffffffu, mx0, 1));
            mx0 = fmaxf(mx0, __shfl_xor_sync(0xffffffffu, mx0, 2));
            mx1 = fmaxf(mx1, __shfl_xor_sync(0xffffffffu, mx1, 1));
            mx1 = fmaxf(mx1, __shfl_xor_sync(0xffffffffu, mx1, 2));
            need = __ballot_sync(0xffffffffu, (mx0 > m_r[0]) | (mx1 > m_r[1]));
            mn0 = fmaxf(m_r[0], mx0);
            mn1 = fmaxf(m_r[1], mx1);
            alpha0 = ex2(m_r[0] - mn0);
            alpha1 = ex2(m_r[1] - mn1);
            m_r[0] = mn0; m_r[1] = mn1;
        }

        // ---- p = exp2(S - m) in half2 (A-fragment layout) + row sums -----
        uint32_t pa[4][4];
        float sum0 = 0.0f, sum1 = 0.0f;
#pragma unroll
        for (int j = 0; j < 4; j++) {
            pa[j][0] = ex2h2(pack2(S[2 * j][0]     - mn0, S[2 * j][1]     - mn0));
            pa[j][1] = ex2h2(pack2(S[2 * j][2]     - mn1, S[2 * j][3]     - mn1));
            pa[j][2] = ex2h2(pack2(S[2 * j + 1][0] - mn0, S[2 * j + 1][1] - mn0));
            pa[j][3] = ex2h2(pack2(S[2 * j + 1][2] - mn1, S[2 * j + 1][3] - mn1));
            float2 f0 = h2f2(pa[j][0]), f1 = h2f2(pa[j][1]);
            float2 f2 = h2f2(pa[j][2]), f3 = h2f2(pa[j][3]);
            sum0 += f0.x + f0.y + f2.x + f2.y;
            sum1 += f1.x + f1.y + f3.x + f3.y;
        }
        sum0 += __shfl_xor_sync(0xffffffffu, sum0, 1);
        sum0 += __shfl_xor_sync(0xffffffffu, sum0, 2);
        sum1 += __shfl_xor_sync(0xffffffffu, sum1, 1);
        sum1 += __shfl_xor_sync(0xffffffffu, sum1, 2);
        l_r[0] = l_r[0] * alpha0 + sum0;
        l_r[1] = l_r[1] * alpha1 + sum1;
        if (need) {
#pragma unroll
            for (int df = 0; df < 8; df++) {
                accO[df][0] *= alpha0; accO[df][1] *= alpha0;
                accO[df][2] *= alpha1; accO[df][3] *= alpha1;
            }
        }

        // ---- O += P @ V --------------------------------------------------
#pragma unroll
        for (int j = 0; j < 4; j++) {
#pragma unroll
            for (int pn = 0; pn < 4; pn++) {
                uint32_t bv[4];
                int rowv = j * 16 + arow;
                ldsm4t(bv, Vst + rowv * 128 + (((2 * pn + ac16) ^ (rowv & 7)) << 4));
                mma_h(accO[2 * pn],     pa[j], bv[0], bv[1]);
                mma_h(accO[2 * pn + 1], pa[j], bv[2], bv[3]);
            }
        }
    }

    // ---- epilogue: half att [B,S,E] --------------------------------------
    float inv0 = 1.0f / l_r[0], inv1 = 1.0f / l_r[1];
    int b = bh >> 4, h = bh & 15;
    int r0 = qt * 64 + wid * 16 + (lane >> 2);
#pragma unroll
    for (int df = 0; df < 8; df++) {
        int d = df * 8 + 2 * (lane & 3);
        size_t a0 = ((size_t)(b * S_LEN + r0)) * EMB + h * 64 + d;
        *(uint32_t*)&O[a0] = pack2(accO[df][0] * inv0, accO[df][1] * inv0);
        *(uint32_t*)&O[a0 + (size_t)8 * EMB] =
            pack2(accO[df][2] * inv1, accO[df][3] * inv1);
    }
}

// ---------------------------------------------------------------------------
extern "C" void kernel_launch(void* const* d_in, const int* in_sizes, int n_in,
                              void* d_out, int out_size)
{
    const float* x  = (const float*)d_in[0];
    const float* Wq = (const float*)d_in[1];
    const float* Wk = (const float*)d_in[2];
    const float* Wv = (const float*)d_in[3];
    const float* Wo = (const float*)d_in[4];
    float* out = (float*)d_out;

    __half *qh, *kh, *vh, *xh, *wh, *atth;
    cudaGetSymbolAddress((void**)&qh,   g_qh);
    cudaGetSymbolAddress((void**)&kh,   g_kh);
    cudaGetSymbolAddress((void**)&vh,   g_vh);
    cudaGetSymbolAddress((void**)&xh,   g_xh);
    cudaGetSymbolAddress((void**)&wh,   g_wh);
    cudaGetSymbolAddress((void**)&atth, g_atth);

    cudaFuncSetAttribute(gemm_h2, cudaFuncAttributeMaxDynamicSharedMemorySize, GSMEM);
    cudaFuncSetAttribute(flash_h, cudaFuncAttributeMaxDynamicSharedMemorySize, FSMEM);

    // one fused conversion pass: x + all four weights (2M float4 units)
    conv_all<<<8192, 256>>>(x, Wq, Wk, Wv, Wo, xh, wh);

    // merged QKV projection: N = 3072
    gemm_h2<<<dim3(24, 32), 128, GSMEM>>>(xh, wh, nullptr, qh, kh, vh, 1);

    rope_h<<<(BATCH * NH * S_LEN * 32) / 256, 256>>>(qh, kh);

    flash_h<<<dim3(S_LEN / 64, BATCH * NH), 128, FSMEM>>>(qh, kh, vh, atth);

    // output projection
    gemm_h2<<<dim3(8, 32), 128, GSMEM>>>(atth, wh + (size_t)3 * EMB * EMB,
                                         out, nullptr, nullptr, nullptr, 0);
}

// round 12
// speedup vs baseline: 1.0768x; 1.0334x over previous
#include <cuda_runtime.h>
#include <cuda_fp16.h>
#include <math.h>
#include <stdint.h>

#define S_LEN 2048
#define EMB   1024
#define NH    16
#define HD    64
#define BATCH 2
#define M_TOK (BATCH * S_LEN)   // 4096

// ---------------- scratch (device globals) ---------------------------------
__device__ __half g_qh[BATCH * NH * S_LEN * HD];  // half [B,H,S,D] (roped+scaled)
__device__ __half g_kh[BATCH * NH * S_LEN * HD];  // half [B,H,S,D] (roped)
__device__ __half g_vh[BATCH * NH * S_LEN * HD];
__device__ __half g_xh[(size_t)M_TOK * EMB];      // half x [4096,1024]
__device__ __half g_wh[4 * EMB * EMB];            // half Wq|Wk|Wv | Wo
__device__ __half g_atth[(size_t)M_TOK * EMB];    // half attn out [B,S,E]
__device__ float2 g_rope[S_LEN * 32];             // (cos,sin)[s][i]

#define QSCALE 0.180336879f   // 0.125 * log2(e)

// ---------------- PTX helpers ----------------------------------------------
__device__ __forceinline__ uint32_t smem_u32(const void* p) {
    uint32_t a;
    asm("{ .reg .u64 t; cvta.to.shared.u64 t, %1; cvt.u32.u64 %0, t; }"
        : "=r"(a) : "l"(p));
    return a;
}
__device__ __forceinline__ void cp16(uint32_t s, const void* g) {
    asm volatile("cp.async.cg.shared.global [%0], [%1], 16;" :: "r"(s), "l"(g) : "memory");
}
__device__ __forceinline__ void cp_commit() {
    asm volatile("cp.async.commit_group;" ::: "memory");
}
#define CP_WAIT(n) asm volatile("cp.async.wait_group %0;" :: "n"(n) : "memory")

__device__ __forceinline__ void ldsm4(uint32_t* r, uint32_t addr) {
    asm volatile("ldmatrix.sync.aligned.m8n8.x4.shared.b16 {%0,%1,%2,%3}, [%4];"
                 : "=r"(r[0]), "=r"(r[1]), "=r"(r[2]), "=r"(r[3]) : "r"(addr));
}
__device__ __forceinline__ void ldsm4t(uint32_t* r, uint32_t addr) {
    asm volatile("ldmatrix.sync.aligned.m8n8.x4.trans.shared.b16 {%0,%1,%2,%3}, [%4];"
                 : "=r"(r[0]), "=r"(r[1]), "=r"(r[2]), "=r"(r[3]) : "r"(addr));
}
__device__ __forceinline__ void mma_h(float* c, const uint32_t* a,
                                      uint32_t b0, uint32_t b1) {
    asm volatile(
        "mma.sync.aligned.m16n8k16.row.col.f32.f16.f16.f32 "
        "{%0,%1,%2,%3}, {%4,%5,%6,%7}, {%8,%9}, {%0,%1,%2,%3};"
        : "+f"(c[0]), "+f"(c[1]), "+f"(c[2]), "+f"(c[3])
        : "r"(a[0]), "r"(a[1]), "r"(a[2]), "r"(a[3]), "r"(b0), "r"(b1));
}
__device__ __forceinline__ uint32_t pack2(float a, float b) {
    __half2 h = __floats2half2_rn(a, b);
    return *reinterpret_cast<uint32_t*>(&h);
}
__device__ __forceinline__ float ex2(float x) {
    float y;
    asm("ex2.approx.ftz.f32 %0, %1;" : "=f"(y) : "f"(x));
    return y;
}
__device__ __forceinline__ uint32_t ex2h2(uint32_t x) {
    uint32_t y;
    asm("ex2.approx.f16x2 %0, %1;" : "=r"(y) : "r"(x));
    return y;
}
__device__ __forceinline__ float2 h2f2(uint32_t h) {
    __half2 hh = *reinterpret_cast<__half2*>(&h);
    return __half22float2(hh);
}

// ---------------------------------------------------------------------------
// Fused fp32->half conversion of x + 4 weights, PLUS rope table build.
// u in [0,1M): x | [1M,2M): weights | [2M, 2M+64K): rope table entries.
// ---------------------------------------------------------------------------
__global__ __launch_bounds__(256) void conv_all(const float* __restrict__ x,
                                                const float* __restrict__ Wq,
                                                const float* __restrict__ Wk,
                                                const float* __restrict__ Wv,
                                                const float* __restrict__ Wo,
                                                __half* __restrict__ xh,
                                                __half* __restrict__ wh,
                                                float2* __restrict__ rope)
{
    int u = blockIdx.x * 256 + threadIdx.x;
    if (u >= (2 << 20)) {
        int idx = u - (2 << 20);
        if (idx < S_LEN * 32) {
            int s = idx >> 5, i = idx & 31;
            float inv_freq = powf(10000.0f, -(float)i * (1.0f / 32.0f));
            float sn, cs;
            sincosf((float)s * inv_freq, &sn, &cs);
            rope[idx] = make_float2(cs, sn);
        }
        return;
    }
    const float* src;
    __half* dst;
    int off;
    if (u < (1 << 20)) { src = x; dst = xh; off = u; }
    else {
        int w = (u - (1 << 20)) >> 18;          // 0..3
        off = (u - (1 << 20)) & ((1 << 18) - 1);
        src = (w == 0) ? Wq : (w == 1) ? Wk : (w == 2) ? Wv : Wo;
        dst = wh + (size_t)w * EMB * EMB;
    }
    float4 v = *(const float4*)&src[off * 4];
    uint2 o;
    o.x = pack2(v.x, v.y);
    o.y = pack2(v.z, v.w);
    *(uint2*)&dst[off * 4] = o;
}

// ---------------------------------------------------------------------------
// half mma GEMM (R9 config, at HMMA ceiling): warp tile 64x64, 4 warps,
// CTA 128x128, 3-stage cp.async, 2 CTAs/SM.
// mode 0: fp32 row-major -> d_out.  mode 1: QKV scatter with FUSED ROPE
// (each warp tile == one head; pair (d, d+32) lives in one thread).
// ---------------------------------------------------------------------------
#define GSMEM (3 * 32768)

__global__ __launch_bounds__(128, 2) void gemm_h2(const __half* __restrict__ A,
                                                  const __half* __restrict__ W,
                                                  const float2* __restrict__ rope,
                                                  float* __restrict__ Cf,
                                                  __half* __restrict__ Qo,
                                                  __half* __restrict__ Ko,
                                                  __half* __restrict__ Vo,
                                                  int mode)
{
    extern __shared__ char smx[];
    const uint32_t sb = smem_u32(smx);
    const int tid = threadIdx.x, wid = tid >> 5, lane = tid & 31;
    const int bn0 = blockIdx.x * 128, bm0 = blockIdx.y * 128;
    const int wm = (wid & 1) * 64, wn = (wid >> 1) * 64;

    const int g = lane >> 3;
    const int arow = (g & 1) * 8 + (lane & 7);
    const int ac16 = g >> 1;
    const int brow = (g >> 1) * 8 + (lane & 7);
    const int bc16 = g & 1;

    auto load = [&](int ck, int st) {
        uint32_t Ab = sb + st * 32768, Bb = Ab + 16384;
#pragma unroll
        for (int j = 0; j < 8; j++) {
            int idx = tid + j * 128;
            int r = idx >> 3, c16 = idx & 7;
            uint32_t sw = (uint32_t)(r * 128) + (uint32_t)((c16 ^ (r & 7)) << 4);
            cp16(Ab + sw, A + (size_t)(bm0 + r) * 1024 + ck * 64 + c16 * 8);
            cp16(Bb + sw, W + (size_t)(bn0 + r) * 1024 + ck * 64 + c16 * 8);
        }
        cp_commit();
    };
    load(0, 0); load(1, 1); load(2, 2);

    float acc[4][8][4];
#pragma unroll
    for (int mb = 0; mb < 4; mb++)
#pragma unroll
        for (int nf = 0; nf < 8; nf++)
#pragma unroll
            for (int i = 0; i < 4; i++) acc[mb][nf][i] = 0.0f;

    for (int c = 0; c < 16; c++) {
        int st = c % 3;
        if (c < 14)       { CP_WAIT(2); }
        else if (c == 14) { CP_WAIT(1); }
        else              { CP_WAIT(0); }
        __syncthreads();

        uint32_t Ab = sb + st * 32768, Bb = Ab + 16384;
#pragma unroll
        for (int ks = 0; ks < 4; ks++) {
            uint32_t af[4][4];
#pragma unroll
            for (int mb = 0; mb < 4; mb++) {
                int row = wm + mb * 16 + arow;
                ldsm4(af[mb], Ab + row * 128 + (((2 * ks + ac16) ^ (row & 7)) << 4));
            }
#pragma unroll
            for (int pn = 0; pn < 4; pn++) {
                uint32_t bf[4];
                int rowb = wn + pn * 16 + brow;
                ldsm4(bf, Bb + rowb * 128 + (((2 * ks + bc16) ^ (rowb & 7)) << 4));
#pragma unroll
                for (int mb = 0; mb < 4; mb++) {
                    mma_h(acc[mb][2 * pn],     af[mb], bf[0], bf[1]);
                    mma_h(acc[mb][2 * pn + 1], af[mb], bf[2], bf[3]);
                }
            }
        }
        __syncthreads();
        if (c + 3 < 16) load(c + 3, st);
    }

    // ---- epilogue ----------------------------------------------------------
    if (mode == 0) {
#pragma unroll
        for (int mb = 0; mb < 4; mb++) {
            int m0 = bm0 + wm + mb * 16 + (lane >> 2);
#pragma unroll
            for (int nf = 0; nf < 8; nf++) {
                int n0 = bn0 + wn + nf * 8 + 2 * (lane & 3);
                *(float2*)&Cf[(size_t)m0 * 1024 + n0] =
                    make_float2(acc[mb][nf][0], acc[mb][nf][1]);
                *(float2*)&Cf[(size_t)(m0 + 8) * 1024 + n0] =
                    make_float2(acc[mb][nf][2], acc[mb][nf][3]);
            }
        }
        return;
    }

    // mode 1: warp tile == one head
    const int proj = (bn0 + wn) >> 10;               // 0=q 1=k 2=v
    const int h = ((bn0 + wn) & 1023) >> 6;
    __half* dstp = (proj == 0) ? Qo : (proj == 1) ? Ko : Vo;

    if (proj == 2) {
#pragma unroll
        for (int mb = 0; mb < 4; mb++) {
            int m0 = bm0 + wm + mb * 16 + (lane >> 2);
#pragma unroll
            for (int nf = 0; nf < 8; nf++) {
                int d = nf * 8 + 2 * (lane & 3);
#pragma unroll
                for (int rr = 0; rr < 2; rr++) {
                    int m = m0 + 8 * rr;
                    int b = m >> 11, s2 = m & 2047;
                    size_t dst = ((((size_t)(b * NH + h) * S_LEN + s2)) << 6) + d;
                    *(uint32_t*)&dstp[dst] =
                        pack2(acc[mb][nf][rr * 2], acc[mb][nf][rr * 2 + 1]);
                }
            }
        }
    } else {
        const float qs = (proj == 0) ? QSCALE : 1.0f;
#pragma unroll
        for (int mb = 0; mb < 4; mb++) {
            int m0 = bm0 + wm + mb * 16 + (lane >> 2);
#pragma unroll
            for (int nf = 0; nf < 4; nf++) {
                int d = nf * 8 + 2 * (lane & 3);   // 0..30, pair at d+32
#pragma unroll
                for (int rr = 0; rr < 2; rr++) {
                    int m = m0 + 8 * rr;
                    int b = m >> 11, s2 = m & 2047;
                    float2 cs0 = rope[s2 * 32 + d];
                    float2 cs1 = rope[s2 * 32 + d + 1];
                    float xl0 = acc[mb][nf][rr * 2],     xl1 = acc[mb][nf][rr * 2 + 1];
                    float xh0 = acc[mb][nf + 4][rr * 2], xh1 = acc[mb][nf + 4][rr * 2 + 1];
                    float ol0 = (xl0 * cs0.x - xh0 * cs0.y) * qs;
                    float ol1 = (xl1 * cs1.x - xh1 * cs1.y) * qs;
                    float oh0 = (xh0 * cs0.x + xl0 * cs0.y) * qs;
                    float oh1 = (xh1 * cs1.x + xl1 * cs1.y) * qs;
                    size_t dst = ((((size_t)(b * NH + h) * S_LEN + s2)) << 6) + d;
                    *(uint32_t*)&dstp[dst]      = pack2(ol0, ol1);
                    *(uint32_t*)&dstp[dst + 32] = pack2(oh0, oh1);
                }
            }
        }
    }
}

// ---------------------------------------------------------------------------
// Causal flash attention v6: 4 warps / 64 q-rows, f16x2 exp2 softmax,
// single barrier/iter, ballot-gated rescale, qf reloaded from smem,
// 5 CTAs/SM (reg cap 102).   smem: Q 8KB | K 2x8KB | V 2x8KB = 40KB
// ---------------------------------------------------------------------------
#define FSMEM (8192 + 16384 + 16384)

__global__ __launch_bounds__(128, 5) void flash_h(const __half* __restrict__ Q,
                                                  const __half* __restrict__ K,
                                                  const __half* __restrict__ V,
                                                  __half* __restrict__ O)
{
    extern __shared__ char smx[];
    const uint32_t sb = smem_u32(smx);
    const int tid = threadIdx.x, wid = tid >> 5, lane = tid & 31;
    const int qt = gridDim.x - 1 - blockIdx.x;   // largest tiles first
    const int bh = blockIdx.y;

    const uint32_t Qs  = sb;
    const uint32_t Ks0 = sb + 8192;
    const uint32_t Vs0 = sb + 24576;

    const __half* Qg = Q + ((size_t)bh * S_LEN + qt * 64) * HD;
    const __half* Kg = K + (size_t)bh * S_LEN * HD;
    const __half* Vg = V + (size_t)bh * S_LEN * HD;

    const int g = lane >> 3;
    const int arow = (g & 1) * 8 + (lane & 7);
    const int ac16 = g >> 1;
    const int brow = (g >> 1) * 8 + (lane & 7);
    const int bc16 = g & 1;

    auto loadKV = [&](int kt, int st) {
#pragma unroll
        for (int j = 0; j < 4; j++) {
            int idx = tid + j * 128;
            int r = idx >> 3, c16 = idx & 7;
            uint32_t sw = (uint32_t)(r * 128) + (uint32_t)((c16 ^ (r & 7)) << 4);
            cp16(Ks0 + st * 8192 + sw, Kg + (size_t)(kt * 64 + r) * HD + c16 * 8);
            cp16(Vs0 + st * 8192 + sw, Vg + (size_t)(kt * 64 + r) * HD + c16 * 8);
        }
        cp_commit();
    };

    // prologue: Q tile + KV tile 0 in one group
#pragma unroll
    for (int j = 0; j < 4; j++) {
        int idx = tid + j * 128;
        int r = idx >> 3, c16 = idx & 7;
        uint32_t sw = (uint32_t)(r * 128) + (uint32_t)((c16 ^ (r & 7)) << 4);
        cp16(Qs + sw, Qg + (size_t)r * HD + c16 * 8);
    }
    loadKV(0, 0);

    float accO[8][4];
#pragma unroll
    for (int d = 0; d < 8; d++)
#pragma unroll
        for (int i = 0; i < 4; i++) accO[d][i] = 0.0f;
    float m_r[2] = {-1e30f, -1e30f};
    float l_r[2] = {0.0f, 0.0f};

    for (int kt = 0; kt <= qt; kt++) {
        const int st = kt & 1;
        CP_WAIT(0);
        __syncthreads();
        if (kt < qt) loadKV(kt + 1, st ^ 1);

        const uint32_t Kst = Ks0 + st * 8192;
        const uint32_t Vst = Vs0 + st * 8192;

        // ---- S = Q @ K^T (qf reloaded from resident Q tile) --------------
        float S[8][4];
#pragma unroll
        for (int n = 0; n < 8; n++)
#pragma unroll
            for (int i = 0; i < 4; i++) S[n][i] = 0.0f;

#pragma unroll
        for (int ks = 0; ks < 4; ks++) {
            uint32_t qf[4];
            {
                int row = wid * 16 + arow;
                ldsm4(qf, Qs + row * 128 + (((2 * ks + ac16) ^ (row & 7)) << 4));
            }
#pragma unroll
            for (int pn = 0; pn < 4; pn++) {
                uint32_t bf[4];
                int rowb = pn * 16 + brow;
                ldsm4(bf, Kst + rowb * 128 + (((2 * ks + bc16) ^ (rowb & 7)) << 4));
                mma_h(S[2 * pn],     qf, bf[0], bf[1]);
                mma_h(S[2 * pn + 1], qf, bf[2], bf[3]);
            }
        }

        // ---- causal mask (single diagonal tile) --------------------------
        if (kt == qt) {
            int rbase = wid * 16 + (lane >> 2);
#pragma unroll
            for (int nf = 0; nf < 8; nf++) {
                int cc = nf * 8 + 2 * (lane & 3);
                if (cc     > rbase)     S[nf][0] = -1e30f;
                if (cc + 1 > rbase)     S[nf][1] = -1e30f;
                if (cc     > rbase + 8) S[nf][2] = -1e30f;
                if (cc + 1 > rbase + 8) S[nf][3] = -1e30f;
            }
        }

        // ---- online softmax (base-2) -------------------------------------
        float mn0, mn1, alpha0, alpha1;
        unsigned need;
        {
            float mx0 = -1e30f, mx1 = -1e30f;
#pragma unroll
            for (int nf = 0; nf < 8; nf++) {
                mx0 = fmaxf(mx0, fmaxf(S[nf][0], S[nf][1]));
                mx1 = fmaxf(mx1, fmaxf(S[nf][2], S[nf][3]));
            }
            mx0 = fmaxf(mx0, __shfl_xor_sync(0xffffffffu, mx0, 1));
            mx0 = fmaxf(mx0, __shfl_xor_sync(0xffffffffu, mx0, 2));
            mx1 = fmaxf(mx1, __shfl_xor_sync(0xffffffffu, mx1, 1));
            mx1 = fmaxf(mx1, __shfl_xor_sync(0xffffffffu, mx1, 2));
            need = __ballot_sync(0xffffffffu, (mx0 > m_r[0]) | (mx1 > m_r[1]));
            mn0 = fmaxf(m_r[0], mx0);
            mn1 = fmaxf(m_r[1], mx1);
            alpha0 = ex2(m_r[0] - mn0);
            alpha1 = ex2(m_r[1] - mn1);
            m_r[0] = mn0; m_r[1] = mn1;
        }

        // ---- p = exp2(S - m) in half2 (A-fragment layout) + row sums -----
        uint32_t pa[4][4];
        float sum0 = 0.0f, sum1 = 0.0f;
#pragma unroll
        for (int j = 0; j < 4; j++) {
            pa[j][0] = ex2h2(pack2(S[2 * j][0]     - mn0, S[2 * j][1]     - mn0));
            pa[j][1] = ex2h2(pack2(S[2 * j][2]     - mn1, S[2 * j][3]     - mn1));
            pa[j][2] = ex2h2(pack2(S[2 * j + 1][0] - mn0, S[2 * j + 1][1] - mn0));
            pa[j][3] = ex2h2(pack2(S[2 * j + 1][2] - mn1, S[2 * j + 1][3] - mn1));
            float2 f0 = h2f2(pa[j][0]), f1 = h2f2(pa[j][1]);
            float2 f2 = h2f2(pa[j][2]), f3 = h2f2(pa[j][3]);
            sum0 += f0.x + f0.y + f2.x + f2.y;
            sum1 += f1.x + f1.y + f3.x + f3.y;
        }
        sum0 += __shfl_xor_sync(0xffffffffu, sum0, 1);
        sum0 += __shfl_xor_sync(0xffffffffu, sum0, 2);
        sum1 += __shfl_xor_sync(0xffffffffu, sum1, 1);
        sum1 += __shfl_xor_sync(0xffffffffu, sum1, 2);
        l_r[0] = l_r[0] * alpha0 + sum0;
        l_r[1] = l_r[1] * alpha1 + sum1;
        if (need) {
#pragma unroll
            for (int df = 0; df < 8; df++) {
                accO[df][0] *= alpha0; accO[df][1] *= alpha0;
                accO[df][2] *= alpha1; accO[df][3] *= alpha1;
            }
        }

        // ---- O += P @ V --------------------------------------------------
#pragma unroll
        for (int j = 0; j < 4; j++) {
#pragma unroll
            for (int pn = 0; pn < 4; pn++) {
                uint32_t bv[4];
                int rowv = j * 16 + arow;
                ldsm4t(bv, Vst + rowv * 128 + (((2 * pn + ac16) ^ (rowv & 7)) << 4));
                mma_h(accO[2 * pn],     pa[j], bv[0], bv[1]);
                mma_h(accO[2 * pn + 1], pa[j], bv[2], bv[3]);
            }
        }
    }

    // ---- epilogue: half att [B,S,E] --------------------------------------
    float inv0 = 1.0f / l_r[0], inv1 = 1.0f / l_r[1];
    int b = bh >> 4, h = bh & 15;
    int r0 = qt * 64 + wid * 16 + (lane >> 2);
#pragma unroll
    for (int df = 0; df < 8; df++) {
        int d = df * 8 + 2 * (lane & 3);
        size_t a0 = ((size_t)(b * S_LEN + r0)) * EMB + h * 64 + d;
        *(uint32_t*)&O[a0] = pack2(accO[df][0] * inv0, accO[df][1] * inv0);
        *(uint32_t*)&O[a0 + (size_t)8 * EMB] =
            pack2(accO[df][2] * inv1, accO[df][3] * inv1);
    }
}

// ---------------------------------------------------------------------------
extern "C" void kernel_launch(void* const* d_in, const int* in_sizes, int n_in,
                              void* d_out, int out_size)
{
    const float* x  = (const float*)d_in[0];
    const float* Wq = (const float*)d_in[1];
    const float* Wk = (const float*)d_in[2];
    const float* Wv = (const float*)d_in[3];
    const float* Wo = (const float*)d_in[4];
    float* out = (float*)d_out;

    __half *qh, *kh, *vh, *xh, *wh, *atth;
    float2* rope;
    cudaGetSymbolAddress((void**)&qh,   g_qh);
    cudaGetSymbolAddress((void**)&kh,   g_kh);
    cudaGetSymbolAddress((void**)&vh,   g_vh);
    cudaGetSymbolAddress((void**)&xh,   g_xh);
    cudaGetSymbolAddress((void**)&wh,   g_wh);
    cudaGetSymbolAddress((void**)&atth, g_atth);
    cudaGetSymbolAddress((void**)&rope, g_rope);

    cudaFuncSetAttribute(gemm_h2, cudaFuncAttributeMaxDynamicSharedMemorySize, GSMEM);
    cudaFuncSetAttribute(flash_h, cudaFuncAttributeMaxDynamicSharedMemorySize, FSMEM);

    // conversions + rope table: 2M float4 units + 64K table entries
    conv_all<<<8448, 256>>>(x, Wq, Wk, Wv, Wo, xh, wh, rope);

    // merged QKV projection (N = 3072) with fused RoPE on q,k
    gemm_h2<<<dim3(24, 32), 128, GSMEM>>>(xh, wh, rope, nullptr, qh, kh, vh, 1);

    flash_h<<<dim3(S_LEN / 64, BATCH * NH), 128, FSMEM>>>(qh, kh, vh, atth);

    // output projection
    gemm_h2<<<dim3(8, 32), 128, GSMEM>>>(atth, wh + (size_t)3 * EMB * EMB,
                                         rope, out, nullptr, nullptr, nullptr, 0);
}

// round 13
// speedup vs baseline: 1.1247x; 1.0444x over previous
#include <cuda_runtime.h>
#include <cuda_fp16.h>
#include <math.h>
#include <stdint.h>

#define S_LEN 2048
#define EMB   1024
#define NH    16
#define HD    64
#define BATCH 2
#define M_TOK (BATCH * S_LEN)   // 4096

// ---------------- scratch (device globals) ---------------------------------
__device__ __half g_qh[BATCH * NH * S_LEN * HD];  // half [B,H,S,D] (roped+scaled)
__device__ __half g_kh[BATCH * NH * S_LEN * HD];  // half [B,H,S,D] (roped)
__device__ __half g_vh[BATCH * NH * S_LEN * HD];
__device__ __half g_xh[(size_t)M_TOK * EMB];      // half x [4096,1024]
__device__ __half g_wh[4 * EMB * EMB];            // half Wq|Wk|Wv | Wo
__device__ __half g_atth[(size_t)M_TOK * EMB];    // half attn out [B,S,E]
__device__ float2 g_rope[S_LEN * 32];             // (cos,sin)[s][i]

#define QSCALE 0.180336879f   // 0.125 * log2(e)
#define ONES_H2 0x3C003C00u   // half2(1.0, 1.0)

// ---------------- PTX helpers ----------------------------------------------
__device__ __forceinline__ uint32_t smem_u32(const void* p) {
    uint32_t a;
    asm("{ .reg .u64 t; cvta.to.shared.u64 t, %1; cvt.u32.u64 %0, t; }"
        : "=r"(a) : "l"(p));
    return a;
}
__device__ __forceinline__ void cp16(uint32_t s, const void* g) {
    asm volatile("cp.async.cg.shared.global [%0], [%1], 16;" :: "r"(s), "l"(g) : "memory");
}
__device__ __forceinline__ void cp_commit() {
    asm volatile("cp.async.commit_group;" ::: "memory");
}
#define CP_WAIT(n) asm volatile("cp.async.wait_group %0;" :: "n"(n) : "memory")

__device__ __forceinline__ void ldsm4(uint32_t* r, uint32_t addr) {
    asm volatile("ldmatrix.sync.aligned.m8n8.x4.shared.b16 {%0,%1,%2,%3}, [%4];"
                 : "=r"(r[0]), "=r"(r[1]), "=r"(r[2]), "=r"(r[3]) : "r"(addr));
}
__device__ __forceinline__ void ldsm4t(uint32_t* r, uint32_t addr) {
    asm volatile("ldmatrix.sync.aligned.m8n8.x4.trans.shared.b16 {%0,%1,%2,%3}, [%4];"
                 : "=r"(r[0]), "=r"(r[1]), "=r"(r[2]), "=r"(r[3]) : "r"(addr));
}
__device__ __forceinline__ void mma_h(float* c, const uint32_t* a,
                                      uint32_t b0, uint32_t b1) {
    asm volatile(
        "mma.sync.aligned.m16n8k16.row.col.f32.f16.f16.f32 "
        "{%0,%1,%2,%3}, {%4,%5,%6,%7}, {%8,%9}, {%0,%1,%2,%3};"
        : "+f"(c[0]), "+f"(c[1]), "+f"(c[2]), "+f"(c[3])
        : "r"(a[0]), "r"(a[1]), "r"(a[2]), "r"(a[3]), "r"(b0), "r"(b1));
}
__device__ __forceinline__ uint32_t pack2(float a, float b) {
    __half2 h = __floats2half2_rn(a, b);
    return *reinterpret_cast<uint32_t*>(&h);
}
__device__ __forceinline__ float ex2(float x) {
    float y;
    asm("ex2.approx.ftz.f32 %0, %1;" : "=f"(y) : "f"(x));
    return y;
}
__device__ __forceinline__ uint32_t ex2h2(uint32_t x) {
    uint32_t y;
    asm("ex2.approx.f16x2 %0, %1;" : "=r"(y) : "r"(x));
    return y;
}

// ---------------------------------------------------------------------------
// Fused fp32->half conversion (MLP=4: 4 float4 per thread) + rope table.
// thread t < 512K: converts float4 units [4t, 4t+4); else rope entry t-512K.
// ---------------------------------------------------------------------------
__global__ __launch_bounds__(256) void conv_all(const float* __restrict__ x,
                                                const float* __restrict__ Wq,
                                                const float* __restrict__ Wk,
                                                const float* __restrict__ Wv,
                                                const float* __restrict__ Wo,
                                                __half* __restrict__ xh,
                                                __half* __restrict__ wh,
                                                float2* __restrict__ rope)
{
    int t = blockIdx.x * 256 + threadIdx.x;
    if (t >= (1 << 19)) {                       // rope range
        int idx = t - (1 << 19);
        if (idx < S_LEN * 32) {
            int s = idx >> 5, i = idx & 31;
            float inv_freq = powf(10000.0f, -(float)i * (1.0f / 32.0f));
            float sn, cs;
            sincosf((float)s * inv_freq, &sn, &cs);
            rope[idx] = make_float2(cs, sn);
        }
        return;
    }
    int gu = t * 4;                             // global float4 unit
    const float* src;
    __half* dst;
    int off;
    if (gu < (1 << 20)) { src = x; dst = xh; off = gu; }
    else {
        int w = (gu - (1 << 20)) >> 18;         // 0..3
        off = (gu - (1 << 20)) & ((1 << 18) - 1);
        src = (w == 0) ? Wq : (w == 1) ? Wk : (w == 2) ? Wv : Wo;
        dst = wh + (size_t)w * EMB * EMB;
    }
    float4 v0 = *(const float4*)&src[(off + 0) * 4];
    float4 v1 = *(const float4*)&src[(off + 1) * 4];
    float4 v2 = *(const float4*)&src[(off + 2) * 4];
    float4 v3 = *(const float4*)&src[(off + 3) * 4];
    uint4 o;
    o.x = pack2(v0.x, v0.y); o.y = pack2(v0.z, v0.w);
    o.z = pack2(v1.x, v1.y); o.w = pack2(v1.z, v1.w);
    *(uint4*)&dst[(off + 0) * 4] = o;
    o.x = pack2(v2.x, v2.y); o.y = pack2(v2.z, v2.w);
    o.z = pack2(v3.x, v3.y); o.w = pack2(v3.z, v3.w);
    *(uint4*)&dst[(off + 2) * 4] = o;
}

// ---------------------------------------------------------------------------
// half mma GEMM (at HMMA plateau): warp tile 64x64, 4 warps, CTA 128x128,
// 3-stage cp.async, 2 CTAs/SM. mode 0: fp32 -> d_out; mode 1: QKV + fused RoPE.
// ---------------------------------------------------------------------------
#define GSMEM (3 * 32768)

__global__ __launch_bounds__(128, 2) void gemm_h2(const __half* __restrict__ A,
                                                  const __half* __restrict__ W,
                                                  const float2* __restrict__ rope,
                                                  float* __restrict__ Cf,
                                                  __half* __restrict__ Qo,
                                                  __half* __restrict__ Ko,
                                                  __half* __restrict__ Vo,
                                                  int mode)
{
    extern __shared__ char smx[];
    const uint32_t sb = smem_u32(smx);
    const int tid = threadIdx.x, wid = tid >> 5, lane = tid & 31;
    const int bn0 = blockIdx.x * 128, bm0 = blockIdx.y * 128;
    const int wm = (wid & 1) * 64, wn = (wid >> 1) * 64;

    const int g = lane >> 3;
    const int arow = (g & 1) * 8 + (lane & 7);
    const int ac16 = g >> 1;
    const int brow = (g >> 1) * 8 + (lane & 7);
    const int bc16 = g & 1;

    auto load = [&](int ck, int st) {
        uint32_t Ab = sb + st * 32768, Bb = Ab + 16384;
#pragma unroll
        for (int j = 0; j < 8; j++) {
            int idx = tid + j * 128;
            int r = idx >> 3, c16 = idx & 7;
            uint32_t sw = (uint32_t)(r * 128) + (uint32_t)((c16 ^ (r & 7)) << 4);
            cp16(Ab + sw, A + (size_t)(bm0 + r) * 1024 + ck * 64 + c16 * 8);
            cp16(Bb + sw, W + (size_t)(bn0 + r) * 1024 + ck * 64 + c16 * 8);
        }
        cp_commit();
    };
    load(0, 0); load(1, 1); load(2, 2);

    float acc[4][8][4];
#pragma unroll
    for (int mb = 0; mb < 4; mb++)
#pragma unroll
        for (int nf = 0; nf < 8; nf++)
#pragma unroll
            for (int i = 0; i < 4; i++) acc[mb][nf][i] = 0.0f;

    for (int c = 0; c < 16; c++) {
        int st = c % 3;
        if (c < 14)       { CP_WAIT(2); }
        else if (c == 14) { CP_WAIT(1); }
        else              { CP_WAIT(0); }
        __syncthreads();

        uint32_t Ab = sb + st * 32768, Bb = Ab + 16384;
#pragma unroll
        for (int ks = 0; ks < 4; ks++) {
            uint32_t af[4][4];
#pragma unroll
            for (int mb = 0; mb < 4; mb++) {
                int row = wm + mb * 16 + arow;
                ldsm4(af[mb], Ab + row * 128 + (((2 * ks + ac16) ^ (row & 7)) << 4));
            }
#pragma unroll
            for (int pn = 0; pn < 4; pn++) {
                uint32_t bf[4];
                int rowb = wn + pn * 16 + brow;
                ldsm4(bf, Bb + rowb * 128 + (((2 * ks + bc16) ^ (rowb & 7)) << 4));
#pragma unroll
                for (int mb = 0; mb < 4; mb++) {
                    mma_h(acc[mb][2 * pn],     af[mb], bf[0], bf[1]);
                    mma_h(acc[mb][2 * pn + 1], af[mb], bf[2], bf[3]);
                }
            }
        }
        __syncthreads();
        if (c + 3 < 16) load(c + 3, st);
    }

    // ---- epilogue ----------------------------------------------------------
    if (mode == 0) {
#pragma unroll
        for (int mb = 0; mb < 4; mb++) {
            int m0 = bm0 + wm + mb * 16 + (lane >> 2);
#pragma unroll
            for (int nf = 0; nf < 8; nf++) {
                int n0 = bn0 + wn + nf * 8 + 2 * (lane & 3);
                *(float2*)&Cf[(size_t)m0 * 1024 + n0] =
                    make_float2(acc[mb][nf][0], acc[mb][nf][1]);
                *(float2*)&Cf[(size_t)(m0 + 8) * 1024 + n0] =
                    make_float2(acc[mb][nf][2], acc[mb][nf][3]);
            }
        }
        return;
    }

    // mode 1: warp tile == one head
    const int proj = (bn0 + wn) >> 10;               // 0=q 1=k 2=v
    const int h = ((bn0 + wn) & 1023) >> 6;
    __half* dstp = (proj == 0) ? Qo : (proj == 1) ? Ko : Vo;

    if (proj == 2) {
#pragma unroll
        for (int mb = 0; mb < 4; mb++) {
            int m0 = bm0 + wm + mb * 16 + (lane >> 2);
#pragma unroll
            for (int nf = 0; nf < 8; nf++) {
                int d = nf * 8 + 2 * (lane & 3);
#pragma unroll
                for (int rr = 0; rr < 2; rr++) {
                    int m = m0 + 8 * rr;
                    int b = m >> 11, s2 = m & 2047;
                    size_t dst = ((((size_t)(b * NH + h) * S_LEN + s2)) << 6) + d;
                    *(uint32_t*)&dstp[dst] =
                        pack2(acc[mb][nf][rr * 2], acc[mb][nf][rr * 2 + 1]);
                }
            }
        }
    } else {
        const float qs = (proj == 0) ? QSCALE : 1.0f;
#pragma unroll
        for (int mb = 0; mb < 4; mb++) {
            int m0 = bm0 + wm + mb * 16 + (lane >> 2);
#pragma unroll
            for (int nf = 0; nf < 4; nf++) {
                int d = nf * 8 + 2 * (lane & 3);   // 0..30, pair at d+32
#pragma unroll
                for (int rr = 0; rr < 2; rr++) {
                    int m = m0 + 8 * rr;
                    int b = m >> 11, s2 = m & 2047;
                    float2 cs0 = rope[s2 * 32 + d];
                    float2 cs1 = rope[s2 * 32 + d + 1];
                    float xl0 = acc[mb][nf][rr * 2],     xl1 = acc[mb][nf][rr * 2 + 1];
                    float xh0 = acc[mb][nf + 4][rr * 2], xh1 = acc[mb][nf + 4][rr * 2 + 1];
                    float ol0 = (xl0 * cs0.x - xh0 * cs0.y) * qs;
                    float ol1 = (xl1 * cs1.x - xh1 * cs1.y) * qs;
                    float oh0 = (xh0 * cs0.x + xl0 * cs0.y) * qs;
                    float oh1 = (xh1 * cs1.x + xl1 * cs1.y) * qs;
                    size_t dst = ((((size_t)(b * NH + h) * S_LEN + s2)) << 6) + d;
                    *(uint32_t*)&dstp[dst]      = pack2(ol0, ol1);
                    *(uint32_t*)&dstp[dst + 32] = pack2(oh0, oh1);
                }
            }
        }
    }
}

// ---------------------------------------------------------------------------
// Causal flash attention v7: 4 warps / 64 q-rows, f16x2 exp2 softmax,
// l computed by P @ ones-MMA (constant B-fragment — no shuffles, no cvts),
// single barrier/iter, ballot-gated rescale, 5 CTAs/SM.
// smem: Q 8KB | K 2x8KB | V 2x8KB = 40KB
// ---------------------------------------------------------------------------
#define FSMEM (8192 + 16384 + 16384)

__global__ __launch_bounds__(128, 5) void flash_h(const __half* __restrict__ Q,
                                                  const __half* __restrict__ K,
                                                  const __half* __restrict__ V,
                                                  __half* __restrict__ O)
{
    extern __shared__ char smx[];
    const uint32_t sb = smem_u32(smx);
    const int tid = threadIdx.x, wid = tid >> 5, lane = tid & 31;
    const int qt = gridDim.x - 1 - blockIdx.x;   // largest tiles first
    const int bh = blockIdx.y;

    const uint32_t Qs  = sb;
    const uint32_t Ks0 = sb + 8192;
    const uint32_t Vs0 = sb + 24576;

    const __half* Qg = Q + ((size_t)bh * S_LEN + qt * 64) * HD;
    const __half* Kg = K + (size_t)bh * S_LEN * HD;
    const __half* Vg = V + (size_t)bh * S_LEN * HD;

    const int g = lane >> 3;
    const int arow = (g & 1) * 8 + (lane & 7);
    const int ac16 = g >> 1;
    const int brow = (g >> 1) * 8 + (lane & 7);
    const int bc16 = g & 1;

    auto loadKV = [&](int kt, int st) {
#pragma unroll
        for (int j = 0; j < 4; j++) {
            int idx = tid + j * 128;
            int r = idx >> 3, c16 = idx & 7;
            uint32_t sw = (uint32_t)(r * 128) + (uint32_t)((c16 ^ (r & 7)) << 4);
            cp16(Ks0 + st * 8192 + sw, Kg + (size_t)(kt * 64 + r) * HD + c16 * 8);
            cp16(Vs0 + st * 8192 + sw, Vg + (size_t)(kt * 64 + r) * HD + c16 * 8);
        }
        cp_commit();
    };

    // prologue: Q tile + KV tile 0 in one group
#pragma unroll
    for (int j = 0; j < 4; j++) {
        int idx = tid + j * 128;
        int r = idx >> 3, c16 = idx & 7;
        uint32_t sw = (uint32_t)(r * 128) + (uint32_t)((c16 ^ (r & 7)) << 4);
        cp16(Qs + sw, Qg + (size_t)r * HD + c16 * 8);
    }
    loadKV(0, 0);

    float accO[8][4];
    float accL[4];                                // P @ ones: row-sum column
#pragma unroll
    for (int d = 0; d < 8; d++)
#pragma unroll
        for (int i = 0; i < 4; i++) accO[d][i] = 0.0f;
#pragma unroll
    for (int i = 0; i < 4; i++) accL[i] = 0.0f;
    float m_r[2] = {-1e30f, -1e30f};

    for (int kt = 0; kt <= qt; kt++) {
        const int st = kt & 1;
        CP_WAIT(0);
        __syncthreads();
        if (kt < qt) loadKV(kt + 1, st ^ 1);

        const uint32_t Kst = Ks0 + st * 8192;
        const uint32_t Vst = Vs0 + st * 8192;

        // ---- S = Q @ K^T (qf reloaded from resident Q tile) --------------
        float S[8][4];
#pragma unroll
        for (int n = 0; n < 8; n++)
#pragma unroll
            for (int i = 0; i < 4; i++) S[n][i] = 0.0f;

#pragma unroll
        for (int ks = 0; ks < 4; ks++) {
            uint32_t qf[4];
            {
                int row = wid * 16 + arow;
                ldsm4(qf, Qs + row * 128 + (((2 * ks + ac16) ^ (row & 7)) << 4));
            }
#pragma unroll
            for (int pn = 0; pn < 4; pn++) {
                uint32_t bf[4];
                int rowb = pn * 16 + brow;
                ldsm4(bf, Kst + rowb * 128 + (((2 * ks + bc16) ^ (rowb & 7)) << 4));
                mma_h(S[2 * pn],     qf, bf[0], bf[1]);
                mma_h(S[2 * pn + 1], qf, bf[2], bf[3]);
            }
        }

        // ---- causal mask (single diagonal tile) --------------------------
        if (kt == qt) {
            int rbase = wid * 16 + (lane >> 2);
#pragma unroll
            for (int nf = 0; nf < 8; nf++) {
                int cc = nf * 8 + 2 * (lane & 3);
                if (cc     > rbase)     S[nf][0] = -1e30f;
                if (cc + 1 > rbase)     S[nf][1] = -1e30f;
                if (cc     > rbase + 8) S[nf][2] = -1e30f;
                if (cc + 1 > rbase + 8) S[nf][3] = -1e30f;
            }
        }

        // ---- online softmax (base-2): row maxes only ---------------------
        float mn0, mn1;
        unsigned need;
        {
            float mx0 = -1e30f, mx1 = -1e30f;
#pragma unroll
            for (int nf = 0; nf < 8; nf++) {
                mx0 = fmaxf(mx0, fmaxf(S[nf][0], S[nf][1]));
                mx1 = fmaxf(mx1, fmaxf(S[nf][2], S[nf][3]));
            }
            mx0 = fmaxf(mx0, __shfl_xor_sync(0xffffffffu, mx0, 1));
            mx0 = fmaxf(mx0, __shfl_xor_sync(0xffffffffu, mx0, 2));
            mx1 = fmaxf(mx1, __shfl_xor_sync(0xffffffffu, mx1, 1));
            mx1 = fmaxf(mx1, __shfl_xor_sync(0xffffffffu, mx1, 2));
            need = __ballot_sync(0xffffffffu, (mx0 > m_r[0]) | (mx1 > m_r[1]));
            mn0 = fmaxf(m_r[0], mx0);
            mn1 = fmaxf(m_r[1], mx1);
            if (need) {
                float alpha0 = ex2(m_r[0] - mn0);
                float alpha1 = ex2(m_r[1] - mn1);
#pragma unroll
                for (int df = 0; df < 8; df++) {
                    accO[df][0] *= alpha0; accO[df][1] *= alpha0;
                    accO[df][2] *= alpha1; accO[df][3] *= alpha1;
                }
                accL[0] *= alpha0; accL[1] *= alpha0;
                accL[2] *= alpha1; accL[3] *= alpha1;
            }
            m_r[0] = mn0; m_r[1] = mn1;
        }

        // ---- p = exp2(S - m) in half2 (A-fragment layout) ----------------
        uint32_t pa[4][4];
#pragma unroll
        for (int j = 0; j < 4; j++) {
            pa[j][0] = ex2h2(pack2(S[2 * j][0]     - mn0, S[2 * j][1]     - mn0));
            pa[j][1] = ex2h2(pack2(S[2 * j][2]     - mn1, S[2 * j][3]     - mn1));
            pa[j][2] = ex2h2(pack2(S[2 * j + 1][0] - mn0, S[2 * j + 1][1] - mn0));
            pa[j][3] = ex2h2(pack2(S[2 * j + 1][2] - mn1, S[2 * j + 1][3] - mn1));
        }

        // ---- O += P @ V ;  l += P @ ones (constant B-frag) ---------------
#pragma unroll
        for (int j = 0; j < 4; j++) {
            mma_h(accL, pa[j], ONES_H2, ONES_H2);
#pragma unroll
            for (int pn = 0; pn < 4; pn++) {
                uint32_t bv[4];
                int rowv = j * 16 + arow;
                ldsm4t(bv, Vst + rowv * 128 + (((2 * pn + ac16) ^ (rowv & 7)) << 4));
                mma_h(accO[2 * pn],     pa[j], bv[0], bv[1]);
                mma_h(accO[2 * pn + 1], pa[j], bv[2], bv[3]);
            }
        }
    }

    // ---- epilogue: half att [B,S,E]; l replicated in accL ----------------
    float inv0 = 1.0f / accL[0], inv1 = 1.0f / accL[2];
    int b = bh >> 4, h = bh & 15;
    int r0 = qt * 64 + wid * 16 + (lane >> 2);
#pragma unroll
    for (int df = 0; df < 8; df++) {
        int d = df * 8 + 2 * (lane & 3);
        size_t a0 = ((size_t)(b * S_LEN + r0)) * EMB + h * 64 + d;
        *(uint32_t*)&O[a0] = pack2(accO[df][0] * inv0, accO[df][1] * inv0);
        *(uint32_t*)&O[a0 + (size_t)8 * EMB] =
            pack2(accO[df][2] * inv1, accO[df][3] * inv1);
    }
}

// ---------------------------------------------------------------------------
extern "C" void kernel_launch(void* const* d_in, const int* in_sizes, int n_in,
                              void* d_out, int out_size)
{
    const float* x  = (const float*)d_in[0];
    const float* Wq = (const float*)d_in[1];
    const float* Wk = (const float*)d_in[2];
    const float* Wv = (const float*)d_in[3];
    const float* Wo = (const float*)d_in[4];
    float* out = (float*)d_out;

    __half *qh, *kh, *vh, *xh, *wh, *atth;
    float2* rope;
    cudaGetSymbolAddress((void**)&qh,   g_qh);
    cudaGetSymbolAddress((void**)&kh,   g_kh);
    cudaGetSymbolAddress((void**)&vh,   g_vh);
    cudaGetSymbolAddress((void**)&xh,   g_xh);
    cudaGetSymbolAddress((void**)&wh,   g_wh);
    cudaGetSymbolAddress((void**)&atth, g_atth);
    cudaGetSymbolAddress((void**)&rope, g_rope);

    cudaFuncSetAttribute(gemm_h2, cudaFuncAttributeMaxDynamicSharedMemorySize, GSMEM);
    cudaFuncSetAttribute(flash_h, cudaFuncAttributeMaxDynamicSharedMemorySize, FSMEM);

    // conversions (MLP=4) + rope table: 512K conv threads + 64K rope threads
    conv_all<<<2304, 256>>>(x, Wq, Wk, Wv, Wo, xh, wh, rope);

    // merged QKV projection (N = 3072) with fused RoPE on q,k
    gemm_h2<<<dim3(24, 32), 128, GSMEM>>>(xh, wh, rope, nullptr, qh, kh, vh, 1);

    flash_h<<<dim3(S_LEN / 64, BATCH * NH), 128, FSMEM>>>(qh, kh, vh, atth);

    // output projection
    gemm_h2<<<dim3(8, 32), 128, GSMEM>>>(atth, wh + (size_t)3 * EMB * EMB,
                                         rope, out, nullptr, nullptr, nullptr, 0);
}